// round 15
// baseline (speedup 1.0000x reference)
#include <cuda_runtime.h>
#include <cuda_bf16.h>
#include <cstdint>
#include <math.h>

// ---------------- problem constants ----------------
#define NB    4
#define NN    8192
#define CO    64
#define KKN   32
#define E_TOT (NB*NN*KKN)     // 1048576
#define TE    128             // edges per tile
#define NTIL  (E_TOT/TE)      // 8192
#define TPBt  (NTIL/NB)       // 2048
#define TPC   4
#define GRIDC (NTIL/TPC)      // 2048
#define NPTS  (E_TOT/KKN)     // 32768
#define PPB   (NPTS/NB)       // 8192
#define MCNT  (NN*KKN)

#define SEGSZ 1040            // padded A-frag segment (512 hi + 512 lo + 16 pad)
#define KS1   3               // conv1 k16-steps (35 -> 48)
#define KSM   4               // mid k16-steps (64)

#define AF1_B (8*KS1*SEGSZ)               // 24960
#define WF1_B (KS1*8*32*16)               // 12288
#define SM1_TOT (AF1_B + WF1_B)           // 37248
#define WFM_B (KSM*8*32*16)               // 16384
#define SMM_TOT (WFM_B + 512)             // 16896

// ---------------- device scratch ----------------
// intermediates in pair-transposed layout: float2 y[pt][cp(32)][e(32)]
__device__ float g_bufA[(size_t)E_TOT * CO];   // 268 MB
__device__ float g_bufB[(size_t)E_TOT * CO];   // 268 MB
__device__ float g_psum[(size_t)NPTS * 2 * CO];  // per half-point partials
__device__ float g_psq [(size_t)NPTS * 2 * CO];
__device__ float g_mx  [(size_t)NPTS * 2 * CO];
__device__ float g_mn  [(size_t)NPTS * 2 * CO];
__device__ float g_scale[NB * CO];
__device__ float g_shift[NB * CO];
__device__ int   g_e32;

// ---------------- bf16 helpers ----------------
__device__ __forceinline__ uint32_t cvt2(float hi_val, float lo_val) {
    uint32_t r;
    asm("cvt.rn.bf16x2.f32 %0, %1, %2;" : "=r"(r) : "f"(hi_val), "f"(lo_val));
    return r;
}
__device__ __forceinline__ float blo(uint32_t p) { return __uint_as_float(p << 16); }
__device__ __forceinline__ float bhi(uint32_t p) { return __uint_as_float(p & 0xffff0000u); }

__device__ __forceinline__ void bsplit2(float x0, float x1, uint32_t& h, uint32_t& l) {
    h = cvt2(x1, x0);
    l = cvt2(x1 - bhi(h), x0 - blo(h));
}

__device__ __forceinline__ void mma16(float* d, const uint4& a, uint32_t b0, uint32_t b1) {
    asm volatile("mma.sync.aligned.m16n8k16.row.col.f32.bf16.bf16.f32 "
        "{%0,%1,%2,%3}, {%4,%5,%6,%7}, {%8,%9}, {%0,%1,%2,%3};"
        : "+f"(d[0]), "+f"(d[1]), "+f"(d[2]), "+f"(d[3])
        : "r"(a.x), "r"(a.y), "r"(a.z), "r"(a.w), "r"(b0), "r"(b1));
}

// A-fragment smem address (conv1 only): element (e, c); hi u32 at p, lo at p+512
__device__ __forceinline__ char* af_addr(char* AF, int nks, int e, int c) {
    int ks = c >> 4, cc = c & 15;
    int reg = ((e >> 3) & 1) | (((cc >> 3) & 1) << 1);
    int lane = ((e & 7) << 2) | ((cc >> 1) & 3);
    return AF + ((e >> 4) * nks + ks) * SEGSZ + lane * 16 + reg * 4;
}

// W fragments: float4 = (bh0, bh1, bl0, bl1) per (ks16, ntile, lane)
__device__ __forceinline__ void build_wfrag(char* WF, const float* __restrict__ Wg,
                                            int CI, int NKS, int KVALID, int t) {
    for (int i = t; i < NKS * 8 * 32; i += 256) {
        int l = i & 31, nt = (i >> 5) & 7, ks = i >> 8;
        int co = nt * 8 + (l >> 2);
        int k0 = ks * 16 + 2 * (l & 3);
        int k2 = k0 + 8;
        float w0 = (k0     < KVALID) ? Wg[co * CI + k0]     : 0.f;
        float w1 = (k0 + 1 < KVALID) ? Wg[co * CI + k0 + 1] : 0.f;
        float w2 = (k2     < KVALID) ? Wg[co * CI + k2]     : 0.f;
        float w3 = (k2 + 1 < KVALID) ? Wg[co * CI + k2 + 1] : 0.f;
        uint32_t bh0, bl0, bh1, bl1;
        bsplit2(w0, w1, bh0, bl0);
        bsplit2(w2, w3, bh1, bl1);
        *(uint4*)(WF + (size_t)i * 16) = make_uint4(bh0, bh1, bl0, bl1);
    }
}

// ---------------- epilogue: store pair-transposed + per-half-point stats ----------------
// warp w: point pt = tile*4 + (w>>1), half = w&1; slot = tile*8 + w
__device__ __forceinline__ void epi_store_pairs(float acc[8][4], float* __restrict__ yout,
                                                int tile, int w, int l) {
    const size_t pt = (size_t)tile * 4 + (w >> 1);
    float2* base = (float2*)yout + pt * 1024;
    const int e0 = (w & 1) * 16 + (l >> 2);
#pragma unroll
    for (int nt = 0; nt < 8; nt++) {
        int cp = nt * 4 + (l & 3);
        base[cp * 32 + e0]     = make_float2(acc[nt][0], acc[nt][1]);
        base[cp * 32 + e0 + 8] = make_float2(acc[nt][2], acc[nt][3]);
    }
}

__device__ __forceinline__ void epi_stats(float acc[8][4], int tile, int w, int l, bool domm) {
    const size_t slot = (size_t)tile * 8 + w;
#pragma unroll
    for (int nt = 0; nt < 8; nt++)
#pragma unroll
        for (int p = 0; p < 2; p++) {
            float v0 = acc[nt][p], v1 = acc[nt][2 + p];
            float s = v0 + v1, q = v0 * v0 + v1 * v1;
            float mx = fmaxf(v0, v1), mn = fminf(v0, v1);
#pragma unroll
            for (int o = 4; o <= 16; o <<= 1) {
                s += __shfl_xor_sync(0xffffffffu, s, o);
                q += __shfl_xor_sync(0xffffffffu, q, o);
                if (domm) {
                    mx = fmaxf(mx, __shfl_xor_sync(0xffffffffu, mx, o));
                    mn = fminf(mn, __shfl_xor_sync(0xffffffffu, mn, o));
                }
            }
            if (l < 4) {
                int c = nt * 8 + l * 2 + p;
                g_psum[slot * CO + c] = s;
                g_psq [slot * CO + c] = q;
                if (domm) {
                    g_mx[slot * CO + c] = mx;
                    g_mn[slot * CO + c] = mn;
                }
            }
        }
}

// ---------------- edges dtype detection ----------------
__global__ void detect_kernel(const long long* __restrict__ e)
{
    int f = 0;
    for (int i = 0; i < 64; i++)
        if (((unsigned long long)e[i]) >> 32) f = 1;
    g_e32 = f;
}

// ---------------- layer 1: gather + concat + GEMM(K=48), smem-staged A ----------------
__global__ __launch_bounds__(256, 3) void conv1_kernel(
    const float* __restrict__ signal, const void* __restrict__ edges,
    const float* __restrict__ efeat,  const float* __restrict__ W1)
{
    extern __shared__ char sm[];
    char* AF = sm;
    char* WF = sm + AF1_B;
    const int t = threadIdx.x, w = t >> 5, l = t & 31;
    const int e32 = g_e32;

    build_wfrag(WF, W1, 35, KS1, 35, t);
    __syncthreads();

    const int el = t >> 1, h = t & 1;

    for (int it = 0; it < TPC; it++) {
        const int tile = blockIdx.x * TPC + it;
        {
            long long ge = (long long)tile * TE + el;
            long long s = e32 ? (long long)((const int*)edges)[ge]
                              : ((const long long*)edges)[ge];
            const float4* row = (const float4*)(signal + s * 32) + h * 4;
#pragma unroll
            for (int m = 0; m < 4; m++) {
                float4 v = row[m];
                uint32_t h01, l01, h23, l23;
                bsplit2(v.x, v.y, h01, l01);
                bsplit2(v.z, v.w, h23, l23);
                char* p = af_addr(AF, KS1, el, h * 16 + 4 * m);
                *(uint32_t*)(p)            = h01;
                *(uint32_t*)(p + 512)      = l01;
                *(uint32_t*)(p + 16)       = h23;
                *(uint32_t*)(p + 512 + 16) = l23;
            }
            if (h == 1) {
                const float* fp = efeat + ge * 3;
                uint32_t h01, l01, h23, l23;
                bsplit2(fp[0], fp[1], h01, l01);
                bsplit2(fp[2], 0.f,   h23, l23);
                char* p = af_addr(AF, KS1, el, 32);
                *(uint32_t*)(p)            = h01;
                *(uint32_t*)(p + 512)      = l01;
                *(uint32_t*)(p + 16)       = h23;
                *(uint32_t*)(p + 512 + 16) = l23;
            } else if (it == 0) {
#pragma unroll
                for (int c = 36; c < 48; c += 2) {
                    char* pz = af_addr(AF, KS1, el, c);
                    *(uint32_t*)(pz)       = 0u;
                    *(uint32_t*)(pz + 512) = 0u;
                }
            }
        }
        __syncthreads();

        float acc[8][4];
#pragma unroll
        for (int nt = 0; nt < 8; nt++)
#pragma unroll
            for (int q = 0; q < 4; q++) acc[nt][q] = 0.f;

#pragma unroll
        for (int ks = 0; ks < KS1; ks++) {
            const char* seg = AF + (w * KS1 + ks) * SEGSZ;
            uint4 ah = *(const uint4*)(seg +       l * 16);
            uint4 al = *(const uint4*)(seg + 512 + l * 16);
#pragma unroll
            for (int nt = 0; nt < 8; nt++) {
                uint4 bv = *(const uint4*)(WF + ((size_t)((ks * 8 + nt) * 32 + l)) * 16);
                mma16(acc[nt], ah, bv.x, bv.y);
                mma16(acc[nt], al, bv.x, bv.y);
                mma16(acc[nt], ah, bv.z, bv.w);
            }
        }

        epi_store_pairs(acc, g_bufA, tile, w, l);
        epi_stats(acc, tile, w, l, false);
        __syncthreads();
    }
}

// ---------------- layers 2/3: fragment-direct LDG + fused norm+lrelu + GEMM(K=64) ----------------
__global__ __launch_bounds__(256, 3) void conv_mid_kernel(int swap, const float* __restrict__ Wg, int mode)
{
    const float* __restrict__ yin = swap ? g_bufB : g_bufA;
    float* __restrict__ yout      = swap ? g_bufA : g_bufB;

    extern __shared__ char sm[];
    char* WF = sm;
    float* s_sc = (float*)(sm + WFM_B);
    float* s_sh = s_sc + CO;
    const int t = threadIdx.x, w = t >> 5, l = t & 31;
    const int b = (blockIdx.x * TPC) / TPBt;

    build_wfrag(WF, Wg, 64, KSM, 64, t);
    if (t < CO) {
        s_sc[t] = g_scale[b * CO + t];
        s_sh[t] = g_shift[b * CO + t];
    }
    __syncthreads();

    const int e0 = (w & 1) * 16 + (l >> 2);
    const int lq = l & 3;

    // per-thread channel affine params (constant across tiles)
    float scA0[KSM], shA0[KSM], scA1[KSM], shA1[KSM];
    float scB0[KSM], shB0[KSM], scB1[KSM], shB1[KSM];
#pragma unroll
    for (int ks = 0; ks < KSM; ks++) {
        int ca = 2 * (ks * 8 + lq);
        int cb = ca + 8;
        scA0[ks] = s_sc[ca];     shA0[ks] = s_sh[ca];
        scA1[ks] = s_sc[ca + 1]; shA1[ks] = s_sh[ca + 1];
        scB0[ks] = s_sc[cb];     shB0[ks] = s_sh[cb];
        scB1[ks] = s_sc[cb + 1]; shB1[ks] = s_sh[cb + 1];
    }

    for (int it = 0; it < TPC; it++) {
        const int tile = blockIdx.x * TPC + it;
        const size_t pt = (size_t)tile * 4 + (w >> 1);
        const float2* __restrict__ base = (const float2*)yin + pt * 1024;

        // load all A data for this tile (16 x LDG.64)
        float2 va[KSM], vb[KSM], vc[KSM], vd[KSM];
#pragma unroll
        for (int ks = 0; ks < KSM; ks++) {
            int cpA = ks * 8 + lq, cpB = cpA + 4;
            va[ks] = base[cpA * 32 + e0];
            vb[ks] = base[cpA * 32 + e0 + 8];
            vc[ks] = base[cpB * 32 + e0];
            vd[ks] = base[cpB * 32 + e0 + 8];
        }

        float acc[8][4];
#pragma unroll
        for (int nt = 0; nt < 8; nt++)
#pragma unroll
            for (int q = 0; q < 4; q++) acc[nt][q] = 0.f;

#pragma unroll
        for (int ks = 0; ks < KSM; ks++) {
            float y0, y1, y2, y3, y4, y5, y6, y7;
            y0 = fmaf(va[ks].x, scA0[ks], shA0[ks]); y0 = y0 >= 0.f ? y0 : 0.1f * y0;
            y1 = fmaf(va[ks].y, scA1[ks], shA1[ks]); y1 = y1 >= 0.f ? y1 : 0.1f * y1;
            y2 = fmaf(vb[ks].x, scA0[ks], shA0[ks]); y2 = y2 >= 0.f ? y2 : 0.1f * y2;
            y3 = fmaf(vb[ks].y, scA1[ks], shA1[ks]); y3 = y3 >= 0.f ? y3 : 0.1f * y3;
            y4 = fmaf(vc[ks].x, scB0[ks], shB0[ks]); y4 = y4 >= 0.f ? y4 : 0.1f * y4;
            y5 = fmaf(vc[ks].y, scB1[ks], shB1[ks]); y5 = y5 >= 0.f ? y5 : 0.1f * y5;
            y6 = fmaf(vd[ks].x, scB0[ks], shB0[ks]); y6 = y6 >= 0.f ? y6 : 0.1f * y6;
            y7 = fmaf(vd[ks].y, scB1[ks], shB1[ks]); y7 = y7 >= 0.f ? y7 : 0.1f * y7;
            uint4 ah, al;
            bsplit2(y0, y1, ah.x, al.x);
            bsplit2(y2, y3, ah.y, al.y);
            bsplit2(y4, y5, ah.z, al.z);
            bsplit2(y6, y7, ah.w, al.w);
#pragma unroll
            for (int nt = 0; nt < 8; nt++) {
                uint4 bv = *(const uint4*)(WF + ((size_t)((ks * 8 + nt) * 32 + l)) * 16);
                mma16(acc[nt], ah, bv.x, bv.y);
                mma16(acc[nt], al, bv.x, bv.y);
                mma16(acc[nt], ah, bv.z, bv.w);
            }
        }

        if (mode == 0) {
            epi_store_pairs(acc, yout, tile, w, l);
            epi_stats(acc, tile, w, l, false);
        } else {
            epi_stats(acc, tile, w, l, true);
        }
    }
}

// ---------------- finalize stats -> fused scale/shift ----------------
__global__ void finalize_kernel(const float* __restrict__ gam, const float* __restrict__ bet)
{
    const int b = blockIdx.x >> 6;
    const int c = blockIdx.x & 63;
    __shared__ float sS[256], sQ[256];
    const int t = threadIdx.x;
    float S = 0.f, Q = 0.f;
    const size_t base = (size_t)b * PPB * 2;
    for (int i = t; i < PPB * 2; i += 256) {
        S += g_psum[(base + i) * CO + c];
        Q += g_psq [(base + i) * CO + c];
    }
    sS[t] = S; sQ[t] = Q;
    __syncthreads();
    for (int off = 128; off > 0; off >>= 1) {
        if (t < off) { sS[t] += sS[t + off]; sQ[t] += sQ[t + off]; }
        __syncthreads();
    }
    if (t == 0) {
        float mu  = sS[0] / (float)MCNT;
        float var = sQ[0] / (float)MCNT - mu * mu;
        float rstd = rsqrtf(var + 1e-5f);
        float scl = gam[c] * rstd;
        g_scale[b * CO + c] = scl;
        g_shift[b * CO + c] = bet[c] - mu * scl;
    }
}

// ---------------- final pool: affine + lrelu on combined max/min ----------------
__global__ __launch_bounds__(256) void pool_kernel(float* __restrict__ out)
{
    const int i = blockIdx.x * 256 + threadIdx.x;   // point*64 + c
    const int p = i >> 6, c = i & 63;
    const int b = p >> 13;
    const float sc = g_scale[b * CO + c];
    const float sh = g_shift[b * CO + c];
    const size_t s0 = (size_t)p * 2 * CO + c;
    float v;
    if (sc >= 0.f) v = fmaxf(g_mx[s0], g_mx[s0 + CO]);
    else           v = fminf(g_mn[s0], g_mn[s0 + CO]);
    float y = fmaf(v, sc, sh);
    out[i] = y >= 0.f ? y : 0.1f * y;
}

// ---------------- launch ----------------
extern "C" void kernel_launch(void* const* d_in, const int* in_sizes, int n_in,
                              void* d_out, int out_size)
{
    const float* signal = (const float*)d_in[0];
    const void*  edges  = d_in[1];
    const float* efeat  = (const float*)d_in[2];
    const int base = (in_sizes[3] == 1) ? 4 : 3;
    const float* W1 = (const float*)d_in[base + 0];
    const float* g1 = (const float*)d_in[base + 1];
    const float* b1 = (const float*)d_in[base + 2];
    const float* W2 = (const float*)d_in[base + 3];
    const float* g2 = (const float*)d_in[base + 4];
    const float* b2 = (const float*)d_in[base + 5];
    const float* W3 = (const float*)d_in[base + 6];
    const float* g3 = (const float*)d_in[base + 7];
    const float* b3 = (const float*)d_in[base + 8];

    cudaFuncSetAttribute(conv1_kernel,    cudaFuncAttributeMaxDynamicSharedMemorySize, SM1_TOT);
    cudaFuncSetAttribute(conv_mid_kernel, cudaFuncAttributeMaxDynamicSharedMemorySize, SMM_TOT);

    detect_kernel<<<1, 1>>>((const long long*)edges);
    conv1_kernel<<<GRIDC, 256, SM1_TOT>>>(signal, edges, efeat, W1);
    finalize_kernel<<<NB * CO, 256>>>(g1, b1);
    conv_mid_kernel<<<GRIDC, 256, SMM_TOT>>>(0, W2, 0);   // A -> B
    finalize_kernel<<<NB * CO, 256>>>(g2, b2);
    conv_mid_kernel<<<GRIDC, 256, SMM_TOT>>>(1, W3, 1);   // B -> max/min
    finalize_kernel<<<NB * CO, 256>>>(g3, b3);
    pool_kernel<<<NPTS * CO / 256, 256>>>((float*)d_out);
}

// round 16
// speedup vs baseline: 1.1694x; 1.1694x over previous
#include <cuda_runtime.h>
#include <cuda_bf16.h>
#include <cstdint>
#include <math.h>

// ---------------- problem constants ----------------
#define NB    4
#define NN    8192
#define CO    64
#define KKN   32
#define E_TOT (NB*NN*KKN)     // 1048576
#define TE    128             // edges per tile
#define NTIL  (E_TOT/TE)      // 8192
#define TPBt  (NTIL/NB)       // 2048
#define TPC   4
#define GRIDC (NTIL/TPC)      // 2048
#define NPTS  (E_TOT/KKN)     // 32768
#define PPB   (NPTS/NB)       // 8192
#define MCNT  (NN*KKN)

#define SEGSZ 1040            // padded A-frag segment (512 hi + 512 lo + 16 pad)
#define KS1   3               // conv1 k16-steps (35 -> 48)
#define KSM   4               // mid k16-steps (64)

#define AF1_B (8*KS1*SEGSZ)               // 24960
#define WF1_B (KS1*8*32*16)               // 12288
#define SM1_TOT (AF1_B + WF1_B)           // 37248
#define AFM_B (8*KSM*SEGSZ)               // 33280
#define WFM_B (KSM*8*32*16)               // 16384
#define SMS_TOT (AFM_B + WFM_B + 512)     // 50176 (stats kernel)
#define SM3_TOT (AFM_B + 2*WFM_B + 1024)  // 67072 (fused conv23)

// ---------------- device scratch ----------------
__device__ float g_bufA[(size_t)E_TOT * CO];       // y1 only (268 MB)
__device__ float g_psum[(size_t)NPTS * 2 * CO];
__device__ float g_psq [(size_t)NPTS * 2 * CO];
__device__ float g_mx  [(size_t)NPTS * 2 * CO];
__device__ float g_mn  [(size_t)NPTS * 2 * CO];
__device__ float g_scaleL[3][NB * CO];
__device__ float g_shiftL[3][NB * CO];
__device__ int   g_e32;

// ---------------- bf16 helpers ----------------
__device__ __forceinline__ uint32_t cvt2(float hi_val, float lo_val) {
    uint32_t r;
    asm("cvt.rn.bf16x2.f32 %0, %1, %2;" : "=r"(r) : "f"(hi_val), "f"(lo_val));
    return r;
}
__device__ __forceinline__ float blo(uint32_t p) { return __uint_as_float(p << 16); }
__device__ __forceinline__ float bhi(uint32_t p) { return __uint_as_float(p & 0xffff0000u); }

__device__ __forceinline__ void bsplit2(float x0, float x1, uint32_t& h, uint32_t& l) {
    h = cvt2(x1, x0);
    l = cvt2(x1 - bhi(h), x0 - blo(h));
}

__device__ __forceinline__ void mma16(float* d, const uint4& a, uint32_t b0, uint32_t b1) {
    asm volatile("mma.sync.aligned.m16n8k16.row.col.f32.bf16.bf16.f32 "
        "{%0,%1,%2,%3}, {%4,%5,%6,%7}, {%8,%9}, {%0,%1,%2,%3};"
        : "+f"(d[0]), "+f"(d[1]), "+f"(d[2]), "+f"(d[3])
        : "r"(a.x), "r"(a.y), "r"(a.z), "r"(a.w), "r"(b0), "r"(b1));
}

// A-fragment smem address: element (e, c); hi u32 at p, lo at p+512
__device__ __forceinline__ char* af_addr(char* AF, int nks, int e, int c) {
    int ks = c >> 4, cc = c & 15;
    int reg = ((e >> 3) & 1) | (((cc >> 3) & 1) << 1);
    int lane = ((e & 7) << 2) | ((cc >> 1) & 3);
    return AF + ((e >> 4) * nks + ks) * SEGSZ + lane * 16 + reg * 4;
}

// W fragments: float4 = (bh0, bh1, bl0, bl1) per (ks16, ntile, lane)
__device__ __forceinline__ void build_wfrag(char* WF, const float* __restrict__ Wg,
                                            int CI, int NKS, int KVALID, int t) {
    for (int i = t; i < NKS * 8 * 32; i += 256) {
        int l = i & 31, nt = (i >> 5) & 7, ks = i >> 8;
        int co = nt * 8 + (l >> 2);
        int k0 = ks * 16 + 2 * (l & 3);
        int k2 = k0 + 8;
        float w0 = (k0     < KVALID) ? Wg[co * CI + k0]     : 0.f;
        float w1 = (k0 + 1 < KVALID) ? Wg[co * CI + k0 + 1] : 0.f;
        float w2 = (k2     < KVALID) ? Wg[co * CI + k2]     : 0.f;
        float w3 = (k2 + 1 < KVALID) ? Wg[co * CI + k2 + 1] : 0.f;
        uint32_t bh0, bl0, bh1, bl1;
        bsplit2(w0, w1, bh0, bl0);
        bsplit2(w2, w3, bh1, bl1);
        *(uint4*)(WF + (size_t)i * 16) = make_uint4(bh0, bh1, bl0, bl1);
    }
}

// ---------------- epilogues (m32n32 shape, conv1/stats) ----------------
__device__ __forceinline__ void epi_store32(float acc[2][4][4], float* __restrict__ yout,
                                            int tile, int wm, int wn, int l) {
    float* base = yout + ((size_t)tile * TE + wm * 32) * CO;
    int r = l >> 2, j2 = (l & 3) * 2;
#pragma unroll
    for (int mt = 0; mt < 2; mt++)
#pragma unroll
        for (int nt = 0; nt < 4; nt++) {
            int c = wn * 32 + nt * 8 + j2;
            *(float2*)&base[(mt * 16 + r)     * CO + c] = make_float2(acc[mt][nt][0], acc[mt][nt][1]);
            *(float2*)&base[(mt * 16 + r + 8) * CO + c] = make_float2(acc[mt][nt][2], acc[mt][nt][3]);
        }
}

__device__ __forceinline__ void epi_stats32(float acc[2][4][4], int tile, int wm, int wn, int l) {
    const size_t pt = (size_t)tile * 4 + wm;   // point slot
#pragma unroll
    for (int nt = 0; nt < 4; nt++)
#pragma unroll
        for (int p = 0; p < 2; p++) {
            float s = 0.f, q = 0.f;
#pragma unroll
            for (int mt = 0; mt < 2; mt++)
#pragma unroll
                for (int hh = 0; hh < 2; hh++) {
                    float v = acc[mt][nt][hh * 2 + p];
                    s += v; q += v * v;
                }
#pragma unroll
            for (int o = 4; o <= 16; o <<= 1) {
                s += __shfl_xor_sync(0xffffffffu, s, o);
                q += __shfl_xor_sync(0xffffffffu, q, o);
            }
            if (l < 4) {
                int c = wn * 32 + nt * 8 + l * 2 + p;
                g_psum[pt * CO + c] = s;
                g_psq [pt * CO + c] = q;
            }
        }
}

// ---------------- epilogue (m16n64 shape, fused conv23): max/min + stats ----------------
__device__ __forceinline__ void epi_stats16(float acc[8][4], int tile, int w, int l) {
    const size_t slot = (size_t)tile * 8 + w;   // half-point slot
#pragma unroll
    for (int nt = 0; nt < 8; nt++)
#pragma unroll
        for (int p = 0; p < 2; p++) {
            float v0 = acc[nt][p], v1 = acc[nt][2 + p];
            float s = v0 + v1, q = v0 * v0 + v1 * v1;
            float mx = fmaxf(v0, v1), mn = fminf(v0, v1);
#pragma unroll
            for (int o = 4; o <= 16; o <<= 1) {
                s += __shfl_xor_sync(0xffffffffu, s, o);
                q += __shfl_xor_sync(0xffffffffu, q, o);
                mx = fmaxf(mx, __shfl_xor_sync(0xffffffffu, mx, o));
                mn = fminf(mn, __shfl_xor_sync(0xffffffffu, mn, o));
            }
            if (l < 4) {
                int c = nt * 8 + l * 2 + p;
                g_psum[slot * CO + c] = s;
                g_psq [slot * CO + c] = q;
                g_mx  [slot * CO + c] = mx;
                g_mn  [slot * CO + c] = mn;
            }
        }
}

// ---------------- edges dtype detection ----------------
__global__ void detect_kernel(const long long* __restrict__ e)
{
    int f = 0;
    for (int i = 0; i < 64; i++)
        if (((unsigned long long)e[i]) >> 32) f = 1;
    g_e32 = f;
}

// ---------------- layer 1: gather + concat + GEMM(K=48) -> y1 + stats ----------------
__global__ __launch_bounds__(256, 3) void conv1_kernel(
    const float* __restrict__ signal, const void* __restrict__ edges,
    const float* __restrict__ efeat,  const float* __restrict__ W1)
{
    extern __shared__ char sm[];
    char* AF = sm;
    char* WF = sm + AF1_B;
    const int t = threadIdx.x, w = t >> 5, l = t & 31;
    const int wm = w & 3, wn = w >> 2;
    const int e32 = g_e32;

    build_wfrag(WF, W1, 35, KS1, 35, t);
    __syncthreads();

    const int el = t >> 1, h = t & 1;

    for (int it = 0; it < TPC; it++) {
        const int tile = blockIdx.x * TPC + it;
        {
            long long ge = (long long)tile * TE + el;
            long long s = e32 ? (long long)((const int*)edges)[ge]
                              : ((const long long*)edges)[ge];
            const float4* row = (const float4*)(signal + s * 32) + h * 4;
#pragma unroll
            for (int m = 0; m < 4; m++) {
                float4 v = row[m];
                uint32_t h01, l01, h23, l23;
                bsplit2(v.x, v.y, h01, l01);
                bsplit2(v.z, v.w, h23, l23);
                char* p = af_addr(AF, KS1, el, h * 16 + 4 * m);
                *(uint32_t*)(p)            = h01;
                *(uint32_t*)(p + 512)      = l01;
                *(uint32_t*)(p + 16)       = h23;
                *(uint32_t*)(p + 512 + 16) = l23;
            }
            if (h == 1) {
                const float* fp = efeat + ge * 3;
                uint32_t h01, l01, h23, l23;
                bsplit2(fp[0], fp[1], h01, l01);
                bsplit2(fp[2], 0.f,   h23, l23);
                char* p = af_addr(AF, KS1, el, 32);
                *(uint32_t*)(p)            = h01;
                *(uint32_t*)(p + 512)      = l01;
                *(uint32_t*)(p + 16)       = h23;
                *(uint32_t*)(p + 512 + 16) = l23;
            } else if (it == 0) {
#pragma unroll
                for (int c = 36; c < 48; c += 2) {
                    char* pz = af_addr(AF, KS1, el, c);
                    *(uint32_t*)(pz)       = 0u;
                    *(uint32_t*)(pz + 512) = 0u;
                }
            }
        }
        __syncthreads();

        float acc[2][4][4];
#pragma unroll
        for (int mt = 0; mt < 2; mt++)
#pragma unroll
            for (int nt = 0; nt < 4; nt++)
#pragma unroll
                for (int q = 0; q < 4; q++) acc[mt][nt][q] = 0.f;

#pragma unroll
        for (int ks = 0; ks < KS1; ks++) {
            const char* seg0 = AF + ((2 * wm)     * KS1 + ks) * SEGSZ;
            const char* seg1 = AF + ((2 * wm + 1) * KS1 + ks) * SEGSZ;
            uint4 ah0 = *(const uint4*)(seg0 +       l * 16);
            uint4 al0 = *(const uint4*)(seg0 + 512 + l * 16);
            uint4 ah1 = *(const uint4*)(seg1 +       l * 16);
            uint4 al1 = *(const uint4*)(seg1 + 512 + l * 16);
#pragma unroll
            for (int nt = 0; nt < 4; nt++) {
                int ntg = wn * 4 + nt;
                uint4 bv = *(const uint4*)(WF + ((size_t)((ks * 8 + ntg) * 32 + l)) * 16);
                mma16(acc[0][nt], ah0, bv.x, bv.y);
                mma16(acc[0][nt], al0, bv.x, bv.y);
                mma16(acc[0][nt], ah0, bv.z, bv.w);
                mma16(acc[1][nt], ah1, bv.x, bv.y);
                mma16(acc[1][nt], al1, bv.x, bv.y);
                mma16(acc[1][nt], ah1, bv.z, bv.w);
            }
        }

        epi_store32(acc, g_bufA, tile, wm, wn, l);
        epi_stats32(acc, tile, wm, wn, l);
        __syncthreads();
    }
}

// ---------------- stats-only pass: y1 -> stats(y2), single-term bf16 ----------------
__global__ __launch_bounds__(256, 3) void stats_mid_kernel(const float* __restrict__ Wg)
{
    extern __shared__ char sm[];
    char* AF = sm;
    char* WF = sm + AFM_B;
    float* s_sc = (float*)(sm + AFM_B + WFM_B);
    float* s_sh = s_sc + CO;
    const int t = threadIdx.x, w = t >> 5, l = t & 31;
    const int wm = w & 3, wn = w >> 2;
    const int b = (blockIdx.x * TPC) / TPBt;

    build_wfrag(WF, Wg, 64, KSM, 64, t);
    if (t < CO) {
        s_sc[t] = g_scaleL[0][b * CO + t];
        s_sh[t] = g_shiftL[0][b * CO + t];
    }
    __syncthreads();

    for (int it = 0; it < TPC; it++) {
        const int tile = blockIdx.x * TPC + it;
        const float4* src = (const float4*)(g_bufA + (size_t)tile * TE * CO);
#pragma unroll
        for (int i = 0; i < 8; i++) {
            int f = i * 256 + t;
            float4 v = src[f];
            int e = f >> 4, c0 = (f & 15) * 4;
            float y0, y1, y2, y3;
            y0 = fmaf(v.x, s_sc[c0 + 0], s_sh[c0 + 0]); y0 = y0 >= 0.f ? y0 : 0.1f * y0;
            y1 = fmaf(v.y, s_sc[c0 + 1], s_sh[c0 + 1]); y1 = y1 >= 0.f ? y1 : 0.1f * y1;
            y2 = fmaf(v.z, s_sc[c0 + 2], s_sh[c0 + 2]); y2 = y2 >= 0.f ? y2 : 0.1f * y2;
            y3 = fmaf(v.w, s_sc[c0 + 3], s_sh[c0 + 3]); y3 = y3 >= 0.f ? y3 : 0.1f * y3;
            char* p = af_addr(AF, KSM, e, c0);
            *(uint32_t*)(p)      = cvt2(y1, y0);   // hi only
            *(uint32_t*)(p + 16) = cvt2(y3, y2);
        }
        __syncthreads();

        float acc[2][4][4];
#pragma unroll
        for (int mt = 0; mt < 2; mt++)
#pragma unroll
            for (int nt = 0; nt < 4; nt++)
#pragma unroll
                for (int q = 0; q < 4; q++) acc[mt][nt][q] = 0.f;

#pragma unroll
        for (int ks = 0; ks < KSM; ks++) {
            const char* seg0 = AF + ((2 * wm)     * KSM + ks) * SEGSZ;
            const char* seg1 = AF + ((2 * wm + 1) * KSM + ks) * SEGSZ;
            uint4 ah0 = *(const uint4*)(seg0 + l * 16);
            uint4 ah1 = *(const uint4*)(seg1 + l * 16);
#pragma unroll
            for (int nt = 0; nt < 4; nt++) {
                int ntg = wn * 4 + nt;
                uint4 bv = *(const uint4*)(WF + ((size_t)((ks * 8 + ntg) * 32 + l)) * 16);
                mma16(acc[0][nt], ah0, bv.x, bv.y);
                mma16(acc[1][nt], ah1, bv.x, bv.y);
            }
        }

        epi_stats32(acc, tile, wm, wn, l);
        __syncthreads();
    }
}

// ---------------- fused conv2+conv3: y1 -> y2 (regs) -> y3 -> max/min + stats ----------------
__global__ __launch_bounds__(256, 2) void conv23_kernel(const float* __restrict__ W2,
                                                        const float* __restrict__ W3)
{
    extern __shared__ char sm[];
    char* AF  = sm;
    char* WF2 = sm + AFM_B;
    char* WF3 = WF2 + WFM_B;
    float* s_sc1 = (float*)(WF3 + WFM_B);
    float* s_sh1 = s_sc1 + CO;
    float* s_sc2 = s_sh1 + CO;
    float* s_sh2 = s_sc2 + CO;
    const int t = threadIdx.x, w = t >> 5, l = t & 31;
    const int b = (blockIdx.x * TPC) / TPBt;

    build_wfrag(WF2, W2, 64, KSM, 64, t);
    build_wfrag(WF3, W3, 64, KSM, 64, t);
    if (t < CO) {
        s_sc1[t] = g_scaleL[0][b * CO + t];
        s_sh1[t] = g_shiftL[0][b * CO + t];
        s_sc2[t] = g_scaleL[1][b * CO + t];
        s_sh2[t] = g_shiftL[1][b * CO + t];
    }
    __syncthreads();

    const int lq2 = 2 * (l & 3);

    for (int it = 0; it < TPC; it++) {
        const int tile = blockIdx.x * TPC + it;
        const float4* src = (const float4*)(g_bufA + (size_t)tile * TE * CO);
#pragma unroll
        for (int i = 0; i < 8; i++) {
            int f = i * 256 + t;
            float4 v = src[f];
            int e = f >> 4, c0 = (f & 15) * 4;
            float y0, y1, y2, y3;
            y0 = fmaf(v.x, s_sc1[c0 + 0], s_sh1[c0 + 0]); y0 = y0 >= 0.f ? y0 : 0.1f * y0;
            y1 = fmaf(v.y, s_sc1[c0 + 1], s_sh1[c0 + 1]); y1 = y1 >= 0.f ? y1 : 0.1f * y1;
            y2 = fmaf(v.z, s_sc1[c0 + 2], s_sh1[c0 + 2]); y2 = y2 >= 0.f ? y2 : 0.1f * y2;
            y3 = fmaf(v.w, s_sc1[c0 + 3], s_sh1[c0 + 3]); y3 = y3 >= 0.f ? y3 : 0.1f * y3;
            uint32_t h01, l01, h23, l23;
            bsplit2(y0, y1, h01, l01);
            bsplit2(y2, y3, h23, l23);
            char* p = af_addr(AF, KSM, e, c0);
            *(uint32_t*)(p)            = h01;
            *(uint32_t*)(p + 512)      = l01;
            *(uint32_t*)(p + 16)       = h23;
            *(uint32_t*)(p + 512 + 16) = l23;
        }
        __syncthreads();

        // phase 1: y2 = W2 x2 — warp = m16 (its 16 edges) x n64
        float acc[8][4];
#pragma unroll
        for (int nt = 0; nt < 8; nt++)
#pragma unroll
            for (int q = 0; q < 4; q++) acc[nt][q] = 0.f;

#pragma unroll
        for (int ks = 0; ks < KSM; ks++) {
            const char* seg = AF + (w * KSM + ks) * SEGSZ;
            uint4 ah = *(const uint4*)(seg +       l * 16);
            uint4 al = *(const uint4*)(seg + 512 + l * 16);
#pragma unroll
            for (int nt = 0; nt < 8; nt++) {
                uint4 bv = *(const uint4*)(WF2 + ((size_t)((ks * 8 + nt) * 32 + l)) * 16);
                mma16(acc[nt], ah, bv.x, bv.y);
                mma16(acc[nt], al, bv.x, bv.y);
                mma16(acc[nt], ah, bv.z, bv.w);
            }
        }

        // phase 2: affine2+lrelu on D-frags -> A-frags in registers -> y3 = W3 x3
        float acc2[8][4];
#pragma unroll
        for (int nt = 0; nt < 8; nt++)
#pragma unroll
            for (int q = 0; q < 4; q++) acc2[nt][q] = 0.f;

#pragma unroll
        for (int q = 0; q < 4; q++) {
            uint4 ah2, al2;
            {
                int j = 2 * q;
                int c0 = 8 * j + lq2, c1 = c0 + 1;
                float sA = s_sc2[c0], hA = s_sh2[c0];
                float sB = s_sc2[c1], hB = s_sh2[c1];
                float y0 = fmaf(acc[j][0], sA, hA); y0 = y0 >= 0.f ? y0 : 0.1f * y0;
                float y1 = fmaf(acc[j][1], sB, hB); y1 = y1 >= 0.f ? y1 : 0.1f * y1;
                float y2 = fmaf(acc[j][2], sA, hA); y2 = y2 >= 0.f ? y2 : 0.1f * y2;
                float y3 = fmaf(acc[j][3], sB, hB); y3 = y3 >= 0.f ? y3 : 0.1f * y3;
                bsplit2(y0, y1, ah2.x, al2.x);
                bsplit2(y2, y3, ah2.y, al2.y);
            }
            {
                int j = 2 * q + 1;
                int c0 = 8 * j + lq2, c1 = c0 + 1;
                float sA = s_sc2[c0], hA = s_sh2[c0];
                float sB = s_sc2[c1], hB = s_sh2[c1];
                float y0 = fmaf(acc[j][0], sA, hA); y0 = y0 >= 0.f ? y0 : 0.1f * y0;
                float y1 = fmaf(acc[j][1], sB, hB); y1 = y1 >= 0.f ? y1 : 0.1f * y1;
                float y2 = fmaf(acc[j][2], sA, hA); y2 = y2 >= 0.f ? y2 : 0.1f * y2;
                float y3 = fmaf(acc[j][3], sB, hB); y3 = y3 >= 0.f ? y3 : 0.1f * y3;
                bsplit2(y0, y1, ah2.z, al2.z);
                bsplit2(y2, y3, ah2.w, al2.w);
            }
#pragma unroll
            for (int nt = 0; nt < 8; nt++) {
                uint4 bv = *(const uint4*)(WF3 + ((size_t)((q * 8 + nt) * 32 + l)) * 16);
                mma16(acc2[nt], ah2, bv.x, bv.y);
                mma16(acc2[nt], al2, bv.x, bv.y);
                mma16(acc2[nt], ah2, bv.z, bv.w);
            }
        }

        epi_stats16(acc2, tile, w, l);
        __syncthreads();
    }
}

// ---------------- finalize stats -> fused scale/shift (per layer) ----------------
__global__ void finalize_kernel(const float* __restrict__ gam, const float* __restrict__ bet,
                                int layer, int spb)
{
    const int b = blockIdx.x >> 6;
    const int c = blockIdx.x & 63;
    __shared__ float sS[256], sQ[256];
    const int t = threadIdx.x;
    float S = 0.f, Q = 0.f;
    const size_t base = (size_t)b * spb;
    for (int i = t; i < spb; i += 256) {
        S += g_psum[(base + i) * CO + c];
        Q += g_psq [(base + i) * CO + c];
    }
    sS[t] = S; sQ[t] = Q;
    __syncthreads();
    for (int off = 128; off > 0; off >>= 1) {
        if (t < off) { sS[t] += sS[t + off]; sQ[t] += sQ[t + off]; }
        __syncthreads();
    }
    if (t == 0) {
        float mu  = sS[0] / (float)MCNT;
        float var = sQ[0] / (float)MCNT - mu * mu;
        float rstd = rsqrtf(var + 1e-5f);
        float scl = gam[c] * rstd;
        g_scaleL[layer][b * CO + c] = scl;
        g_shiftL[layer][b * CO + c] = bet[c] - mu * scl;
    }
}

// ---------------- final pool: affine + lrelu on combined max/min ----------------
__global__ __launch_bounds__(256) void pool_kernel(float* __restrict__ out)
{
    const int i = blockIdx.x * 256 + threadIdx.x;   // point*64 + c
    const int p = i >> 6, c = i & 63;
    const int b = p >> 13;
    const float sc = g_scaleL[2][b * CO + c];
    const float sh = g_shiftL[2][b * CO + c];
    const size_t s0 = (size_t)p * 2 * CO + c;
    float v;
    if (sc >= 0.f) v = fmaxf(g_mx[s0], g_mx[s0 + CO]);
    else           v = fminf(g_mn[s0], g_mn[s0 + CO]);
    float y = fmaf(v, sc, sh);
    out[i] = y >= 0.f ? y : 0.1f * y;
}

// ---------------- launch ----------------
extern "C" void kernel_launch(void* const* d_in, const int* in_sizes, int n_in,
                              void* d_out, int out_size)
{
    const float* signal = (const float*)d_in[0];
    const void*  edges  = d_in[1];
    const float* efeat  = (const float*)d_in[2];
    const int base = (in_sizes[3] == 1) ? 4 : 3;
    const float* W1 = (const float*)d_in[base + 0];
    const float* g1 = (const float*)d_in[base + 1];
    const float* b1 = (const float*)d_in[base + 2];
    const float* W2 = (const float*)d_in[base + 3];
    const float* g2 = (const float*)d_in[base + 4];
    const float* b2 = (const float*)d_in[base + 5];
    const float* W3 = (const float*)d_in[base + 6];
    const float* g3 = (const float*)d_in[base + 7];
    const float* b3 = (const float*)d_in[base + 8];

    cudaFuncSetAttribute(conv1_kernel,     cudaFuncAttributeMaxDynamicSharedMemorySize, SM1_TOT);
    cudaFuncSetAttribute(stats_mid_kernel, cudaFuncAttributeMaxDynamicSharedMemorySize, SMS_TOT);
    cudaFuncSetAttribute(conv23_kernel,    cudaFuncAttributeMaxDynamicSharedMemorySize, SM3_TOT);

    detect_kernel<<<1, 1>>>((const long long*)edges);
    conv1_kernel<<<GRIDC, 256, SM1_TOT>>>(signal, edges, efeat, W1);
    finalize_kernel<<<NB * CO, 256>>>(g1, b1, 0, PPB);
    stats_mid_kernel<<<GRIDC, 256, SMS_TOT>>>(W2);
    finalize_kernel<<<NB * CO, 256>>>(g2, b2, 1, PPB);
    conv23_kernel<<<GRIDC, 256, SM3_TOT>>>(W2, W3);
    finalize_kernel<<<NB * CO, 256>>>(g3, b3, 2, PPB * 2);
    pool_kernel<<<NPTS * CO / 256, 256>>>((float*)d_out);
}